// round 1
// baseline (speedup 1.0000x reference)
#include <cuda_runtime.h>
#include <math.h>

#define Bv  4
#define Tv  2048
#define Cv  2048
#define Hv  16
#define HDv 128
#define BHv (Bv*Hv)

// ---------------- scratch (device globals; no allocation allowed) ----------------
__device__ float g_q[(size_t)BHv * Tv * HDv];  // [b,h,t,d]
__device__ float g_k[(size_t)BHv * Tv * HDv];
__device__ float g_v[(size_t)BHv * Tv * HDv];
__device__ float g_y[(size_t)Bv * Tv * Cv];    // attention out, [b,t,c]

// ---------------- SGEMM: out[r,o] = sum_c A[r,c] * W[o,c] ----------------
// BM=BN=64, BK=16, 256 threads, 4x4 per-thread tile.
// dst_mode: 0->g_q, 1->g_k, 2->g_v (scatter to [b,h,t,d]), 3->Oext plain [r,o]
// src_mode: 0->Aext, 1->g_y
__global__ void sgemm_kernel(const float* __restrict__ Aext,
                             const float* __restrict__ W,
                             float* __restrict__ Oext,
                             int src_mode, int dst_mode)
{
    __shared__ float As[16][64];
    __shared__ float Bs[16][64];

    const float* A = (src_mode == 0) ? Aext : g_y;

    int bm = blockIdx.y * 64;
    int bn = blockIdx.x * 64;
    int tid = threadIdx.x;
    int tx = tid & 15;
    int ty = tid >> 4;
    int lm = tid >> 2;          // 0..63
    int lk = (tid & 3) * 4;     // 0,4,8,12

    const float* aptr = A + (size_t)(bm + lm) * Cv + lk;
    const float* bptr = W + (size_t)(bn + lm) * Cv + lk;

    float acc[4][4] = {};

    for (int k0 = 0; k0 < Cv; k0 += 16) {
        float4 va = *(const float4*)(aptr + k0);
        float4 vb = *(const float4*)(bptr + k0);
        As[lk + 0][lm] = va.x; As[lk + 1][lm] = va.y;
        As[lk + 2][lm] = va.z; As[lk + 3][lm] = va.w;
        Bs[lk + 0][lm] = vb.x; Bs[lk + 1][lm] = vb.y;
        Bs[lk + 2][lm] = vb.z; Bs[lk + 3][lm] = vb.w;
        __syncthreads();
#pragma unroll
        for (int k = 0; k < 16; k++) {
            float a[4], b[4];
            *(float4*)a = *(const float4*)&As[k][ty * 4];
            *(float4*)b = *(const float4*)&Bs[k][tx * 4];
#pragma unroll
            for (int i = 0; i < 4; i++)
#pragma unroll
                for (int j = 0; j < 4; j++)
                    acc[i][j] += a[i] * b[j];
        }
        __syncthreads();
    }

    if (dst_mode == 3) {
#pragma unroll
        for (int i = 0; i < 4; i++)
#pragma unroll
            for (int j = 0; j < 4; j++)
                Oext[(size_t)(bm + ty * 4 + i) * Cv + (bn + tx * 4 + j)] = acc[i][j];
    } else {
        float* outp = (dst_mode == 0) ? g_q : (dst_mode == 1) ? g_k : g_v;
#pragma unroll
        for (int i = 0; i < 4; i++) {
            int r = bm + ty * 4 + i;
            int b = r >> 11;          // r / T
            int t = r & 2047;         // r % T
#pragma unroll
            for (int j = 0; j < 4; j++) {
                int o = bn + tx * 4 + j;
                int h = o >> 7;       // o / 128
                int d = o & 127;      // o % 128
                outp[(((size_t)(b * Hv + h) * Tv) + t) * HDv + d] = acc[i][j];
            }
        }
    }
}

// ---------------- RoPE (in place on g_q, g_k) ----------------
__global__ void rope_kernel()
{
    int idx = blockIdx.x * blockDim.x + threadIdx.x;   // BH*T*64 = 8388608
    int i  = idx & 63;
    int t  = (idx >> 6) & 2047;
    int bh = idx >> 17;
    if (bh >= BHv) return;

    float inv = (float)pow(10000.0, -(double)i / 64.0);
    float f = (float)t * inv;
    float c, s;
    __sincosf(f, &s, &c);
    // replicate fp32-accurate sin/cos (use precise versions; cheap vs GEMMs)
    c = cosf(f); s = sinf(f);

    size_t base = ((size_t)bh * Tv + t) * HDv;
    float q1 = g_q[base + i], q2 = g_q[base + i + 64];
    g_q[base + i]      = q1 * c - q2 * s;
    g_q[base + i + 64] = q2 * c + q1 * s;
    float k1 = g_k[base + i], k2 = g_k[base + i + 64];
    g_k[base + i]      = k1 * c - k2 * s;
    g_k[base + i + 64] = k2 * c + k1 * s;
}

// ---------------- Flash attention, fp32, causal ----------------
// Grid: (qtile=32, bh=64). 256 threads = 16x16 (tx,ty).
// Tiles: Q/K/V 64x128 (padded stride 132), S/P 64x64 (stride 65).
#define SQ_STRIDE 132
#define SS_STRIDE 65
#define ATT_SMEM_FLOATS (3 * 64 * SQ_STRIDE + 64 * SS_STRIDE + 64 * 16 + 3 * 64)
#define ATT_SMEM_BYTES  (ATT_SMEM_FLOATS * 4)

__global__ void attn_kernel()
{
    extern __shared__ float sm[];
    float* sQ   = sm;
    float* sK   = sQ + 64 * SQ_STRIDE;
    float* sV   = sK + 64 * SQ_STRIDE;
    float* sS   = sV + 64 * SQ_STRIDE;
    float* sred = sS + 64 * SS_STRIDE;     // [64][16]
    float* srm  = sred + 64 * 16;          // running max
    float* sra  = srm + 64;                // alpha
    float* srl  = sra + 64;                // running denom

    int bh = blockIdx.y;
    int qb = blockIdx.x;
    int q0 = qb * 64;
    int tid = threadIdx.x;
    int tx = tid & 15;
    int ty = tid >> 4;
    size_t base = (size_t)bh * Tv * HDv;

    // load Q tile (64 rows x 128) as float4
    for (int i = tid; i < 64 * 32; i += 256) {
        int r  = i >> 5;
        int d4 = (i & 31) * 4;
        *(float4*)&sQ[r * SQ_STRIDE + d4] =
            *(const float4*)&g_q[base + (size_t)(q0 + r) * HDv + d4];
    }
    if (tid < 64) { srm[tid] = -1e30f; srl[tid] = 0.0f; }
    float acc[4][8] = {};
    __syncthreads();

    const float scale = 0.08838834764831845f;  // 1/sqrt(128)

    for (int kt = 0; kt <= qb; kt++) {
        int k0 = kt * 64;
        for (int i = tid; i < 64 * 32; i += 256) {
            int r  = i >> 5;
            int d4 = (i & 31) * 4;
            *(float4*)&sK[r * SQ_STRIDE + d4] =
                *(const float4*)&g_k[base + (size_t)(k0 + r) * HDv + d4];
            *(float4*)&sV[r * SQ_STRIDE + d4] =
                *(const float4*)&g_v[base + (size_t)(k0 + r) * HDv + d4];
        }
        __syncthreads();

        // ---- scores S = Q K^T (4x4 per thread) ----
        float s[4][4] = {};
#pragma unroll 8
        for (int d = 0; d < 128; d += 4) {
            float qv[4][4], kv[4][4];
#pragma unroll
            for (int i = 0; i < 4; i++)
                *(float4*)qv[i] = *(const float4*)&sQ[(ty * 4 + i) * SQ_STRIDE + d];
#pragma unroll
            for (int j = 0; j < 4; j++)
                *(float4*)kv[j] = *(const float4*)&sK[(tx * 4 + j) * SQ_STRIDE + d];
#pragma unroll
            for (int i = 0; i < 4; i++)
#pragma unroll
                for (int j = 0; j < 4; j++)
#pragma unroll
                    for (int dd = 0; dd < 4; dd++)
                        s[i][j] += qv[i][dd] * kv[j][dd];
        }

        bool diag = (kt == qb);
#pragma unroll
        for (int i = 0; i < 4; i++)
#pragma unroll
            for (int j = 0; j < 4; j++) {
                s[i][j] *= scale;
                if (diag && (k0 + tx * 4 + j) > (q0 + ty * 4 + i)) s[i][j] = -1e30f;
            }

        // ---- row max partial reduce ----
#pragma unroll
        for (int i = 0; i < 4; i++) {
            float rm = fmaxf(fmaxf(s[i][0], s[i][1]), fmaxf(s[i][2], s[i][3]));
            sred[(ty * 4 + i) * 16 + tx] = rm;
        }
        __syncthreads();
        if (tid < 64) {
            float m = srm[tid];
            float tm = -1e30f;
#pragma unroll
            for (int x = 0; x < 16; x++) tm = fmaxf(tm, sred[tid * 16 + x]);
            float mn = fmaxf(m, tm);
            srm[tid] = mn;
            sra[tid] = __expf(m - mn);
        }
        __syncthreads();

        // ---- P = exp(S - m), write to sS, partial row sums, rescale acc ----
#pragma unroll
        for (int i = 0; i < 4; i++) {
            float mn = srm[ty * 4 + i];
            float rs = 0.0f;
#pragma unroll
            for (int j = 0; j < 4; j++) {
                float p = __expf(s[i][j] - mn);
                sS[(ty * 4 + i) * SS_STRIDE + tx * 4 + j] = p;
                rs += p;
            }
            sred[(ty * 4 + i) * 16 + tx] = rs;
        }
#pragma unroll
        for (int i = 0; i < 4; i++) {
            float a = sra[ty * 4 + i];
#pragma unroll
            for (int c = 0; c < 8; c++) acc[i][c] *= a;
        }
        __syncthreads();

        if (tid < 64) {
            float ssum = 0.0f;
#pragma unroll
            for (int x = 0; x < 16; x++) ssum += sred[tid * 16 + x];
            srl[tid] = srl[tid] * sra[tid] + ssum;
        }

        // ---- O += P @ V ----
#pragma unroll 4
        for (int k = 0; k < 64; k++) {
            float pv[4];
#pragma unroll
            for (int i = 0; i < 4; i++) pv[i] = sS[(ty * 4 + i) * SS_STRIDE + k];
            float vv[8];
            *(float4*)&vv[0] = *(const float4*)&sV[k * SQ_STRIDE + tx * 8];
            *(float4*)&vv[4] = *(const float4*)&sV[k * SQ_STRIDE + tx * 8 + 4];
#pragma unroll
            for (int i = 0; i < 4; i++)
#pragma unroll
                for (int c = 0; c < 8; c++)
                    acc[i][c] += pv[i] * vv[c];
        }
        __syncthreads();
    }

    // ---- epilogue: divide by l, write [b,t,c] ----
    int b = bh >> 4;
    int h = bh & 15;
#pragma unroll
    for (int i = 0; i < 4; i++) {
        float invl = 1.0f / srl[ty * 4 + i];
        int t = q0 + ty * 4 + i;
        float* op = g_y + ((size_t)(b * Tv + t)) * Cv + h * HDv + tx * 8;
#pragma unroll
        for (int c = 0; c < 8; c++) op[c] = acc[i][c] * invl;
    }
}

// ---------------- launch ----------------
extern "C" void kernel_launch(void* const* d_in, const int* in_sizes, int n_in,
                              void* d_out, int out_size)
{
    const float* x  = (const float*)d_in[0];
    // d_in[1] = mask (causal, known statically; unused)
    const float* wq = (const float*)d_in[2];
    const float* wk = (const float*)d_in[3];
    const float* wv = (const float*)d_in[4];
    const float* wo = (const float*)d_in[5];
    float* out = (float*)d_out;

    dim3 gg(Cv / 64, (Bv * Tv) / 64);  // (32, 128)

    sgemm_kernel<<<gg, 256>>>(x, wq, nullptr, 0, 0);
    sgemm_kernel<<<gg, 256>>>(x, wk, nullptr, 0, 1);
    sgemm_kernel<<<gg, 256>>>(x, wv, nullptr, 0, 2);

    rope_kernel<<<(BHv * Tv * 64) / 256, 256>>>();

    cudaFuncSetAttribute(attn_kernel, cudaFuncAttributeMaxDynamicSharedMemorySize,
                         ATT_SMEM_BYTES);
    attn_kernel<<<dim3(Tv / 64, BHv), 256, ATT_SMEM_BYTES>>>();

    sgemm_kernel<<<gg, 256>>>(nullptr, wo, out, 1, 3);
}

// round 2
// speedup vs baseline: 1.6057x; 1.6057x over previous
#include <cuda_runtime.h>
#include <math.h>

#define Bv  4
#define Tv  2048
#define Cv  2048
#define Hv  16
#define HDv 128
#define BHv (Bv*Hv)

// ---------------- scratch (device globals; no allocation allowed) ----------------
__device__ float g_q[(size_t)BHv * Tv * HDv];  // [b,h,t,d]
__device__ float g_k[(size_t)BHv * Tv * HDv];
__device__ float g_v[(size_t)BHv * Tv * HDv];
__device__ float g_y[(size_t)Bv * Tv * Cv];    // attention out, [b,t,c]

__device__ __forceinline__ unsigned f2tf(float f) {
    unsigned u;
    asm("cvt.rna.tf32.f32 %0, %1;" : "=r"(u) : "f"(f));
    return u;
}

__device__ __forceinline__ void mma_tf32(float* c, const unsigned* a, const unsigned* b) {
    asm volatile(
        "mma.sync.aligned.m16n8k8.row.col.f32.tf32.tf32.f32 "
        "{%0,%1,%2,%3}, {%4,%5,%6,%7}, {%8,%9}, {%0,%1,%2,%3};\n"
        : "+f"(c[0]), "+f"(c[1]), "+f"(c[2]), "+f"(c[3])
        : "r"(a[0]), "r"(a[1]), "r"(a[2]), "r"(a[3]), "r"(b[0]), "r"(b[1]));
}

// ---------------- tf32 tensor-core GEMM: out[r,o] = sum_c A[r,c] * W[o,c] ----------
// Block tile 128x128, BK=16, 256 threads (8 warps as 4x2), warp tile 32x64.
// dst_mode: 0->g_q, 1->g_k, 2->g_v (scatter to [b,h,t,d]), 3->Oext plain [r,o]
// src_mode: 0->Aext, 1->g_y
__global__ void tf32gemm_kernel(const float* __restrict__ Aext,
                                const float* __restrict__ W,
                                float* __restrict__ Oext,
                                int src_mode, int dst_mode)
{
    __shared__ unsigned As[16][132];   // [k][m]
    __shared__ unsigned Bs[16][132];   // [k][n]

    const float* A = (src_mode == 0) ? Aext : g_y;

    int bm = blockIdx.y * 128;
    int bn = blockIdx.x * 128;
    int tid = threadIdx.x;
    int lane = tid & 31;
    int wid = tid >> 5;
    int wm = (wid & 3) * 32;   // warp row offset
    int wn = (wid >> 2) * 64;  // warp col offset
    int g  = lane >> 2;        // group id 0..7
    int tg = lane & 3;         // thread-in-group 0..3

    int lr = tid >> 2;         // 0..63 (load row)
    int lc = (tid & 3) * 4;    // 0,4,8,12 (load col base)

    const float* aptr = A + (size_t)(bm + lr) * Cv + lc;
    const float* bptr = W + (size_t)(bn + lr) * Cv + lc;

    float c[2][8][4];
#pragma unroll
    for (int i = 0; i < 2; i++)
#pragma unroll
        for (int j = 0; j < 8; j++)
#pragma unroll
            for (int e = 0; e < 4; e++) c[i][j][e] = 0.0f;

    for (int k0 = 0; k0 < Cv; k0 += 16) {
        float4 va0 = *(const float4*)(aptr + k0);
        float4 va1 = *(const float4*)(aptr + (size_t)64 * Cv + k0);
        float4 vb0 = *(const float4*)(bptr + k0);
        float4 vb1 = *(const float4*)(bptr + (size_t)64 * Cv + k0);

        As[lc + 0][lr] = f2tf(va0.x); As[lc + 1][lr] = f2tf(va0.y);
        As[lc + 2][lr] = f2tf(va0.z); As[lc + 3][lr] = f2tf(va0.w);
        As[lc + 0][lr + 64] = f2tf(va1.x); As[lc + 1][lr + 64] = f2tf(va1.y);
        As[lc + 2][lr + 64] = f2tf(va1.z); As[lc + 3][lr + 64] = f2tf(va1.w);
        Bs[lc + 0][lr] = f2tf(vb0.x); Bs[lc + 1][lr] = f2tf(vb0.y);
        Bs[lc + 2][lr] = f2tf(vb0.z); Bs[lc + 3][lr] = f2tf(vb0.w);
        Bs[lc + 0][lr + 64] = f2tf(vb1.x); Bs[lc + 1][lr + 64] = f2tf(vb1.y);
        Bs[lc + 2][lr + 64] = f2tf(vb1.z); Bs[lc + 3][lr + 64] = f2tf(vb1.w);
        __syncthreads();

#pragma unroll
        for (int ks = 0; ks < 16; ks += 8) {
            unsigned a[2][4], b[8][2];
#pragma unroll
            for (int i = 0; i < 2; i++) {
                int r0 = wm + i * 16 + g;
                a[i][0] = As[ks + tg][r0];
                a[i][1] = As[ks + tg][r0 + 8];
                a[i][2] = As[ks + tg + 4][r0];
                a[i][3] = As[ks + tg + 4][r0 + 8];
            }
#pragma unroll
            for (int j = 0; j < 8; j++) {
                int n0 = wn + j * 8 + g;
                b[j][0] = Bs[ks + tg][n0];
                b[j][1] = Bs[ks + tg + 4][n0];
            }
#pragma unroll
            for (int i = 0; i < 2; i++)
#pragma unroll
                for (int j = 0; j < 8; j++)
                    mma_tf32(c[i][j], a[i], b[j]);
        }
        __syncthreads();
    }

    // ---- epilogue ----
    if (dst_mode == 3) {
#pragma unroll
        for (int i = 0; i < 2; i++)
#pragma unroll
            for (int j = 0; j < 8; j++) {
                int r = bm + wm + i * 16 + g;
                int o = bn + wn + j * 8 + tg * 2;
                *(float2*)&Oext[(size_t)r * Cv + o] = make_float2(c[i][j][0], c[i][j][1]);
                *(float2*)&Oext[(size_t)(r + 8) * Cv + o] = make_float2(c[i][j][2], c[i][j][3]);
            }
    } else {
        float* outp = (dst_mode == 0) ? g_q : (dst_mode == 1) ? g_k : g_v;
#pragma unroll
        for (int i = 0; i < 2; i++)
#pragma unroll
            for (int j = 0; j < 8; j++) {
                int r = bm + wm + i * 16 + g;
                int o = bn + wn + j * 8 + tg * 2;
                int b_ = r >> 11;      // r / T
                int t  = r & 2047;     // r % T
                int h  = o >> 7;       // o / 128
                int d  = o & 127;      // o % 128
                size_t off = (((size_t)(b_ * Hv + h) * Tv) + t) * HDv + d;
                *(float2*)&outp[off] = make_float2(c[i][j][0], c[i][j][1]);
                *(float2*)&outp[off + (size_t)8 * HDv] = make_float2(c[i][j][2], c[i][j][3]);
            }
    }
}

// ---------------- RoPE (in place on g_q, g_k) ----------------
__global__ void rope_kernel()
{
    int idx = blockIdx.x * blockDim.x + threadIdx.x;   // BH*T*64
    int i  = idx & 63;
    int t  = (idx >> 6) & 2047;
    int bh = idx >> 17;
    if (bh >= BHv) return;

    float inv = (float)pow(10000.0, -(double)i / 64.0);
    float f = (float)t * inv;
    float c = cosf(f), s = sinf(f);

    size_t base = ((size_t)bh * Tv + t) * HDv;
    float q1 = g_q[base + i], q2 = g_q[base + i + 64];
    g_q[base + i]      = q1 * c - q2 * s;
    g_q[base + i + 64] = q2 * c + q1 * s;
    float k1 = g_k[base + i], k2 = g_k[base + i + 64];
    g_k[base + i]      = k1 * c - k2 * s;
    g_k[base + i + 64] = k2 * c + k1 * s;
}

// ---------------- Flash attention, fp32, causal ----------------
#define SQ_STRIDE 132
#define SS_STRIDE 65
#define ATT_SMEM_FLOATS (3 * 64 * SQ_STRIDE + 64 * SS_STRIDE + 64 * 16 + 3 * 64)
#define ATT_SMEM_BYTES  (ATT_SMEM_FLOATS * 4)

__global__ void attn_kernel()
{
    extern __shared__ float sm[];
    float* sQ   = sm;
    float* sK   = sQ + 64 * SQ_STRIDE;
    float* sV   = sK + 64 * SQ_STRIDE;
    float* sS   = sV + 64 * SQ_STRIDE;
    float* sred = sS + 64 * SS_STRIDE;     // [64][16]
    float* srm  = sred + 64 * 16;          // running max
    float* sra  = srm + 64;                // alpha
    float* srl  = sra + 64;                // running denom

    int bh = blockIdx.y;
    int qb = blockIdx.x;
    int q0 = qb * 64;
    int tid = threadIdx.x;
    int tx = tid & 15;
    int ty = tid >> 4;
    size_t base = (size_t)bh * Tv * HDv;

    for (int i = tid; i < 64 * 32; i += 256) {
        int r  = i >> 5;
        int d4 = (i & 31) * 4;
        *(float4*)&sQ[r * SQ_STRIDE + d4] =
            *(const float4*)&g_q[base + (size_t)(q0 + r) * HDv + d4];
    }
    if (tid < 64) { srm[tid] = -1e30f; srl[tid] = 0.0f; }
    float acc[4][8] = {};
    __syncthreads();

    const float scale = 0.08838834764831845f;  // 1/sqrt(128)

    for (int kt = 0; kt <= qb; kt++) {
        int k0 = kt * 64;
        for (int i = tid; i < 64 * 32; i += 256) {
            int r  = i >> 5;
            int d4 = (i & 31) * 4;
            *(float4*)&sK[r * SQ_STRIDE + d4] =
                *(const float4*)&g_k[base + (size_t)(k0 + r) * HDv + d4];
            *(float4*)&sV[r * SQ_STRIDE + d4] =
                *(const float4*)&g_v[base + (size_t)(k0 + r) * HDv + d4];
        }
        __syncthreads();

        float s[4][4] = {};
#pragma unroll 8
        for (int d = 0; d < 128; d += 4) {
            float qv[4][4], kv[4][4];
#pragma unroll
            for (int i = 0; i < 4; i++)
                *(float4*)qv[i] = *(const float4*)&sQ[(ty * 4 + i) * SQ_STRIDE + d];
#pragma unroll
            for (int j = 0; j < 4; j++)
                *(float4*)kv[j] = *(const float4*)&sK[(tx * 4 + j) * SQ_STRIDE + d];
#pragma unroll
            for (int i = 0; i < 4; i++)
#pragma unroll
                for (int j = 0; j < 4; j++)
#pragma unroll
                    for (int dd = 0; dd < 4; dd++)
                        s[i][j] += qv[i][dd] * kv[j][dd];
        }

        bool diag = (kt == qb);
#pragma unroll
        for (int i = 0; i < 4; i++)
#pragma unroll
            for (int j = 0; j < 4; j++) {
                s[i][j] *= scale;
                if (diag && (k0 + tx * 4 + j) > (q0 + ty * 4 + i)) s[i][j] = -1e30f;
            }

#pragma unroll
        for (int i = 0; i < 4; i++) {
            float rm = fmaxf(fmaxf(s[i][0], s[i][1]), fmaxf(s[i][2], s[i][3]));
            sred[(ty * 4 + i) * 16 + tx] = rm;
        }
        __syncthreads();
        if (tid < 64) {
            float m = srm[tid];
            float tm = -1e30f;
#pragma unroll
            for (int x = 0; x < 16; x++) tm = fmaxf(tm, sred[tid * 16 + x]);
            float mn = fmaxf(m, tm);
            srm[tid] = mn;
            sra[tid] = __expf(m - mn);
        }
        __syncthreads();

#pragma unroll
        for (int i = 0; i < 4; i++) {
            float mn = srm[ty * 4 + i];
            float rs = 0.0f;
#pragma unroll
            for (int j = 0; j < 4; j++) {
                float p = __expf(s[i][j] - mn);
                sS[(ty * 4 + i) * SS_STRIDE + tx * 4 + j] = p;
                rs += p;
            }
            sred[(ty * 4 + i) * 16 + tx] = rs;
        }
#pragma unroll
        for (int i = 0; i < 4; i++) {
            float a = sra[ty * 4 + i];
#pragma unroll
            for (int cc = 0; cc < 8; cc++) acc[i][cc] *= a;
        }
        __syncthreads();

        if (tid < 64) {
            float ssum = 0.0f;
#pragma unroll
            for (int x = 0; x < 16; x++) ssum += sred[tid * 16 + x];
            srl[tid] = srl[tid] * sra[tid] + ssum;
        }

#pragma unroll 4
        for (int k = 0; k < 64; k++) {
            float pv[4];
#pragma unroll
            for (int i = 0; i < 4; i++) pv[i] = sS[(ty * 4 + i) * SS_STRIDE + k];
            float vv[8];
            *(float4*)&vv[0] = *(const float4*)&sV[k * SQ_STRIDE + tx * 8];
            *(float4*)&vv[4] = *(const float4*)&sV[k * SQ_STRIDE + tx * 8 + 4];
#pragma unroll
            for (int i = 0; i < 4; i++)
#pragma unroll
                for (int cc = 0; cc < 8; cc++)
                    acc[i][cc] += pv[i] * vv[cc];
        }
        __syncthreads();
    }

    int b = bh >> 4;
    int h = bh & 15;
#pragma unroll
    for (int i = 0; i < 4; i++) {
        float invl = 1.0f / srl[ty * 4 + i];
        int t = q0 + ty * 4 + i;
        float* op = g_y + ((size_t)(b * Tv + t)) * Cv + h * HDv + tx * 8;
#pragma unroll
        for (int cc = 0; cc < 8; cc++) op[cc] = acc[i][cc] * invl;
    }
}

// ---------------- launch ----------------
extern "C" void kernel_launch(void* const* d_in, const int* in_sizes, int n_in,
                              void* d_out, int out_size)
{
    const float* x  = (const float*)d_in[0];
    // d_in[1] = mask (causal, known statically; unused)
    const float* wq = (const float*)d_in[2];
    const float* wk = (const float*)d_in[3];
    const float* wv = (const float*)d_in[4];
    const float* wo = (const float*)d_in[5];
    float* out = (float*)d_out;

    dim3 gg(Cv / 128, (Bv * Tv) / 128);  // (16, 64)

    tf32gemm_kernel<<<gg, 256>>>(x, wq, nullptr, 0, 0);
    tf32gemm_kernel<<<gg, 256>>>(x, wk, nullptr, 0, 1);
    tf32gemm_kernel<<<gg, 256>>>(x, wv, nullptr, 0, 2);

    rope_kernel<<<(BHv * Tv * 64) / 256, 256>>>();

    cudaFuncSetAttribute(attn_kernel, cudaFuncAttributeMaxDynamicSharedMemorySize,
                         ATT_SMEM_BYTES);
    attn_kernel<<<dim3(Tv / 64, BHv), 256, ATT_SMEM_BYTES>>>();

    tf32gemm_kernel<<<gg, 256>>>(nullptr, wo, out, 1, 3);
}

// round 3
// speedup vs baseline: 2.0139x; 1.2542x over previous
#include <cuda_runtime.h>
#include <math.h>

#define Bv  4
#define Tv  2048
#define Cv  2048
#define Hv  16
#define HDv 128
#define BHv (Bv*Hv)

// ---------------- scratch (device globals; no allocation allowed) ----------------
__device__ float g_q[(size_t)BHv * Tv * HDv];  // [b,h,t,d]
__device__ float g_k[(size_t)BHv * Tv * HDv];
__device__ float g_v[(size_t)BHv * Tv * HDv];
__device__ float g_y[(size_t)Bv * Tv * Cv];    // attention out, [b,t,c]

__device__ __forceinline__ unsigned f2tf(float f) {
    unsigned u;
    asm("cvt.rna.tf32.f32 %0, %1;" : "=r"(u) : "f"(f));
    return u;
}

__device__ __forceinline__ void mma4(float* c, const uint4& a, const uint2& b) {
    asm volatile(
        "mma.sync.aligned.m16n8k8.row.col.f32.tf32.tf32.f32 "
        "{%0,%1,%2,%3}, {%4,%5,%6,%7}, {%8,%9}, {%0,%1,%2,%3};\n"
        : "+f"(c[0]), "+f"(c[1]), "+f"(c[2]), "+f"(c[3])
        : "r"(a.x), "r"(a.y), "r"(a.z), "r"(a.w), "r"(b.x), "r"(b.y));
}

// ================= tf32 GEMM: out[r,o] = sum_c A[r,c] * W[o,c] =================
// Block 128x128, BK=16, 256 threads (8 warps 4x2, warp tile 32x64).
// smem holds tiles in mma-FRAGMENT order: A frags load as LDS.128, B as LDS.64.
// Double-buffered smem stages.
// A-frag addr for elem (m,k):  ((k>>3)*8 + (m>>4))*128 + ((m&7)*4 + (k&3))*4
//                               + ( ((m>>3)&1) | (((k>>2)&1)<<1) )
// B-frag addr for elem (n,k):  ((k>>3)*16 + (n>>3))*64 + ((n&7)*4 + (k&3))*2
//                               + ((k>>2)&1)
__global__ void tf32gemm_kernel(const float* __restrict__ Aext,
                                const float* __restrict__ W,
                                float* __restrict__ Oext,
                                int src_mode, int dst_mode)
{
    __shared__ unsigned sA[2][2048];
    __shared__ unsigned sB[2][2048];

    const float* A = (src_mode == 0) ? Aext : g_y;

    int bm = blockIdx.y * 128;
    int bn = blockIdx.x * 128;
    int tid = threadIdx.x;
    int lane = tid & 31;
    int wid = tid >> 5;
    int g = lane >> 2;
    int tg = lane & 3;
    int lr = tid >> 2;          // 0..63
    int lc = (tid & 3) * 4;     // 0,4,8,12

    const float* aptr = A + (size_t)(bm + lr) * Cv + lc;
    const float* bptr = W + (size_t)(bn + lr) * Cv + lc;

    // staging offsets (k-chunk-local)
    int aoff0 = ((lc >> 3) * 8 + (lr >> 4)) * 128 + (lr & 7) * 16
              + (((lr >> 3) & 1) | (((lc >> 2) & 1) << 1));
    int aoff1 = aoff0 + 512;   // row lr+64 -> mtile+4
    int boff0 = ((lc >> 3) * 16 + (lr >> 3)) * 64 + (lr & 7) * 8 + ((lc >> 2) & 1);
    int boff1 = boff0 + 512;   // row lr+64 -> ntile+8

    int mt0 = (wid & 3) * 2;
    int nt0 = (wid >> 2) * 8;

    float c[2][8][4];
#pragma unroll
    for (int i = 0; i < 2; i++)
#pragma unroll
        for (int j = 0; j < 8; j++)
#pragma unroll
            for (int e = 0; e < 4; e++) c[i][j][e] = 0.0f;

    // prologue: stage k-chunk 0
    {
        float4 va0 = *(const float4*)(aptr);
        float4 va1 = *(const float4*)(aptr + (size_t)64 * Cv);
        float4 vb0 = *(const float4*)(bptr);
        float4 vb1 = *(const float4*)(bptr + (size_t)64 * Cv);
        sA[0][aoff0 + 0] = f2tf(va0.x); sA[0][aoff0 + 4]  = f2tf(va0.y);
        sA[0][aoff0 + 8] = f2tf(va0.z); sA[0][aoff0 + 12] = f2tf(va0.w);
        sA[0][aoff1 + 0] = f2tf(va1.x); sA[0][aoff1 + 4]  = f2tf(va1.y);
        sA[0][aoff1 + 8] = f2tf(va1.z); sA[0][aoff1 + 12] = f2tf(va1.w);
        sB[0][boff0 + 0] = f2tf(vb0.x); sB[0][boff0 + 2]  = f2tf(vb0.y);
        sB[0][boff0 + 4] = f2tf(vb0.z); sB[0][boff0 + 6]  = f2tf(vb0.w);
        sB[0][boff1 + 0] = f2tf(vb1.x); sB[0][boff1 + 2]  = f2tf(vb1.y);
        sB[0][boff1 + 4] = f2tf(vb1.z); sB[0][boff1 + 6]  = f2tf(vb1.w);
    }
    __syncthreads();

    const int NIT = Cv / 16;   // 128
    for (int it = 0; it < NIT; it++) {
        float4 va0, va1, vb0, vb1;
        if (it + 1 < NIT) {
            size_t k0 = (size_t)(it + 1) * 16;
            va0 = *(const float4*)(aptr + k0);
            va1 = *(const float4*)(aptr + (size_t)64 * Cv + k0);
            vb0 = *(const float4*)(bptr + k0);
            vb1 = *(const float4*)(bptr + (size_t)64 * Cv + k0);
        }

        const unsigned* SA = sA[it & 1];
        const unsigned* SB = sB[it & 1];
#pragma unroll
        for (int ks = 0; ks < 2; ks++) {
            uint4 a0 = *(const uint4*)&SA[(ks * 8 + mt0) * 128 + lane * 4];
            uint4 a1 = *(const uint4*)&SA[(ks * 8 + mt0 + 1) * 128 + lane * 4];
#pragma unroll
            for (int j = 0; j < 8; j++) {
                uint2 b = *(const uint2*)&SB[(ks * 16 + nt0 + j) * 64 + lane * 2];
                mma4(c[0][j], a0, b);
                mma4(c[1][j], a1, b);
            }
        }
        __syncthreads();

        if (it + 1 < NIT) {
            unsigned* WA = sA[(it + 1) & 1];
            unsigned* WB = sB[(it + 1) & 1];
            WA[aoff0 + 0] = f2tf(va0.x); WA[aoff0 + 4]  = f2tf(va0.y);
            WA[aoff0 + 8] = f2tf(va0.z); WA[aoff0 + 12] = f2tf(va0.w);
            WA[aoff1 + 0] = f2tf(va1.x); WA[aoff1 + 4]  = f2tf(va1.y);
            WA[aoff1 + 8] = f2tf(va1.z); WA[aoff1 + 12] = f2tf(va1.w);
            WB[boff0 + 0] = f2tf(vb0.x); WB[boff0 + 2]  = f2tf(vb0.y);
            WB[boff0 + 4] = f2tf(vb0.z); WB[boff0 + 6]  = f2tf(vb0.w);
            WB[boff1 + 0] = f2tf(vb1.x); WB[boff1 + 2]  = f2tf(vb1.y);
            WB[boff1 + 4] = f2tf(vb1.z); WB[boff1 + 6]  = f2tf(vb1.w);
            __syncthreads();
        }
    }

    int wm = (wid & 3) * 32;
    int wn = (wid >> 2) * 64;

    if (dst_mode == 3) {
#pragma unroll
        for (int i = 0; i < 2; i++)
#pragma unroll
            for (int j = 0; j < 8; j++) {
                int r = bm + wm + i * 16 + g;
                int o = bn + wn + j * 8 + tg * 2;
                *(float2*)&Oext[(size_t)r * Cv + o] = make_float2(c[i][j][0], c[i][j][1]);
                *(float2*)&Oext[(size_t)(r + 8) * Cv + o] = make_float2(c[i][j][2], c[i][j][3]);
            }
    } else {
        float* outp = (dst_mode == 0) ? g_q : (dst_mode == 1) ? g_k : g_v;
#pragma unroll
        for (int i = 0; i < 2; i++)
#pragma unroll
            for (int j = 0; j < 8; j++) {
                int r = bm + wm + i * 16 + g;
                int o = bn + wn + j * 8 + tg * 2;
                int b_ = r >> 11;
                int t  = r & 2047;
                int h  = o >> 7;
                int d  = o & 127;
                size_t off = (((size_t)(b_ * Hv + h) * Tv) + t) * HDv + d;
                *(float2*)&outp[off] = make_float2(c[i][j][0], c[i][j][1]);
                *(float2*)&outp[off + (size_t)8 * HDv] = make_float2(c[i][j][2], c[i][j][3]);
            }
    }
}

// ---------------- RoPE (in place on g_q, g_k) ----------------
__global__ void rope_kernel()
{
    int idx = blockIdx.x * blockDim.x + threadIdx.x;
    int i  = idx & 63;
    int t  = (idx >> 6) & 2047;
    int bh = idx >> 17;
    if (bh >= BHv) return;

    float inv = (float)pow(10000.0, -(double)i / 64.0);
    float f = (float)t * inv;
    float c = cosf(f), s = sinf(f);

    size_t base = ((size_t)bh * Tv + t) * HDv;
    float q1 = g_q[base + i], q2 = g_q[base + i + 64];
    g_q[base + i]      = q1 * c - q2 * s;
    g_q[base + i + 64] = q2 * c + q1 * s;
    float k1 = g_k[base + i], k2 = g_k[base + i + 64];
    g_k[base + i]      = k1 * c - k2 * s;
    g_k[base + i + 64] = k2 * c + k1 * s;
}

// ================= TF32 flash attention, causal =================
// CTA: 64 q-rows, 4 warps (each owns one m16 tile -> warp-local softmax).
// smem (all in mma fragment order):
//   sQ [64x128] A-frag   : 8192 u32
//   sK [n=64(s), k=128(d)] B-frag : 8192 u32
//   sV [n=128(d), k=64(s)] B-frag : 8192 u32
//   sP per-warp [16x64] A-frag : 4 x 1024 u32
#define ATT_SMEM_U32  (8192 * 3 + 4096)
#define ATT_SMEM_BYTES (ATT_SMEM_U32 * 4)

__global__ void attn_kernel()
{
    extern __shared__ unsigned sm[];
    unsigned* sQ = sm;
    unsigned* sK = sQ + 8192;
    unsigned* sV = sK + 8192;
    unsigned* sP = sV + 8192;

    int bh = blockIdx.y;
    int qb = blockIdx.x;
    int q0 = qb * 64;
    int tid = threadIdx.x;
    int lane = tid & 31;
    int w = tid >> 5;
    int g = lane >> 2;
    int tg = lane & 3;
    size_t base = (size_t)bh * Tv * HDv;

    // stage Q (fragment order): 64x128 -> 2048 float4 / 128 threads
    for (int i = tid; i < 2048; i += 128) {
        int r  = i >> 5;
        int d0 = (i & 31) * 4;
        float4 v = *(const float4*)&g_q[base + (size_t)(q0 + r) * HDv + d0];
        int addr = ((d0 >> 3) * 4 + (r >> 4)) * 128 + (r & 7) * 16
                 + (((r >> 3) & 1) | (((d0 >> 2) & 1) << 1));
        sQ[addr + 0] = f2tf(v.x); sQ[addr + 4]  = f2tf(v.y);
        sQ[addr + 8] = f2tf(v.z); sQ[addr + 12] = f2tf(v.w);
    }

    float o[16][4];
#pragma unroll
    for (int nt = 0; nt < 16; nt++)
#pragma unroll
        for (int e = 0; e < 4; e++) o[nt][e] = 0.0f;
    float mrow0 = -1e30f, mrow1 = -1e30f;
    float lrow0 = 0.0f,   lrow1 = 0.0f;

    const float scale = 0.08838834764831845f;  // 1/sqrt(128)
    unsigned* Pw = sP + w * 1024;

    for (int kt = 0; kt <= qb; kt++) {
        __syncthreads();   // protect sK/sV (and sQ on first iter)
        int k0 = kt * 64;
        for (int i = tid; i < 2048; i += 128) {
            int r  = i >> 5;
            int d0 = (i & 31) * 4;
            const float* kp = &g_k[base + (size_t)(k0 + r) * HDv + d0];
            const float* vp = &g_v[base + (size_t)(k0 + r) * HDv + d0];
            float4 vk = *(const float4*)kp;
            float4 vv = *(const float4*)vp;
            // K as B-frag (n=r, k=d)
            int ak = ((d0 >> 3) * 8 + (r >> 3)) * 64 + (r & 7) * 8 + ((d0 >> 2) & 1);
            sK[ak + 0] = f2tf(vk.x); sK[ak + 2] = f2tf(vk.y);
            sK[ak + 4] = f2tf(vk.z); sK[ak + 6] = f2tf(vk.w);
            // V as B-frag (n=d, k=r)
            int av = ((r >> 3) * 16 + (d0 >> 3)) * 64 + ((d0 & 7) * 4 + (r & 3)) * 2
                   + ((r >> 2) & 1);
            sV[av + 0]  = f2tf(vv.x); sV[av + 8]  = f2tf(vv.y);
            sV[av + 16] = f2tf(vv.z); sV[av + 24] = f2tf(vv.w);
        }
        __syncthreads();

        // ---- S = Q K^T (warp-local m16 x n64 x k128) ----
        float s[8][4];
#pragma unroll
        for (int nt = 0; nt < 8; nt++)
#pragma unroll
            for (int e = 0; e < 4; e++) s[nt][e] = 0.0f;
#pragma unroll
        for (int ks = 0; ks < 16; ks++) {
            uint4 aq = *(const uint4*)&sQ[(ks * 4 + w) * 128 + lane * 4];
#pragma unroll
            for (int nt = 0; nt < 8; nt++) {
                uint2 bk = *(const uint2*)&sK[(ks * 8 + nt) * 64 + lane * 2];
                mma4(s[nt], aq, bk);
            }
        }

        // ---- scale + causal mask ----
        bool diag = (kt == qb);
        int row0 = q0 + w * 16 + g;
#pragma unroll
        for (int nt = 0; nt < 8; nt++) {
#pragma unroll
            for (int e2 = 0; e2 < 4; e2++) {
                float v = s[nt][e2] * scale;
                if (diag) {
                    int col = k0 + nt * 8 + tg * 2 + (e2 & 1);
                    int row = row0 + (e2 >> 1) * 8;
                    if (col > row) v = -1e30f;
                }
                s[nt][e2] = v;
            }
        }

        // ---- warp-local row max (rows g and g+8) ----
        float mx0 = -1e30f, mx1 = -1e30f;
#pragma unroll
        for (int nt = 0; nt < 8; nt++) {
            mx0 = fmaxf(mx0, fmaxf(s[nt][0], s[nt][1]));
            mx1 = fmaxf(mx1, fmaxf(s[nt][2], s[nt][3]));
        }
        mx0 = fmaxf(mx0, __shfl_xor_sync(0xffffffffu, mx0, 1));
        mx0 = fmaxf(mx0, __shfl_xor_sync(0xffffffffu, mx0, 2));
        mx1 = fmaxf(mx1, __shfl_xor_sync(0xffffffffu, mx1, 1));
        mx1 = fmaxf(mx1, __shfl_xor_sync(0xffffffffu, mx1, 2));

        float mn0 = fmaxf(mrow0, mx0);
        float mn1 = fmaxf(mrow1, mx1);
        float al0 = __expf(mrow0 - mn0);
        float al1 = __expf(mrow1 - mn1);
        mrow0 = mn0; mrow1 = mn1;

        // ---- p = exp(s - m), row sums, store P in A-frag order ----
        float rs0 = 0.0f, rs1 = 0.0f;
#pragma unroll
        for (int nt = 0; nt < 8; nt++) {
            float p0 = __expf(s[nt][0] - mn0);
            float p1 = __expf(s[nt][1] - mn0);
            float p2 = __expf(s[nt][2] - mn1);
            float p3 = __expf(s[nt][3] - mn1);
            rs0 += p0 + p1; rs1 += p2 + p3;
            s[nt][0] = p0; s[nt][1] = p1; s[nt][2] = p2; s[nt][3] = p3;
        }
        rs0 += __shfl_xor_sync(0xffffffffu, rs0, 1);
        rs0 += __shfl_xor_sync(0xffffffffu, rs0, 2);
        rs1 += __shfl_xor_sync(0xffffffffu, rs1, 1);
        rs1 += __shfl_xor_sync(0xffffffffu, rs1, 2);
        lrow0 = lrow0 * al0 + rs0;
        lrow1 = lrow1 * al1 + rs1;

        // rescale O
#pragma unroll
        for (int nt = 0; nt < 16; nt++) {
            o[nt][0] *= al0; o[nt][1] *= al0;
            o[nt][2] *= al1; o[nt][3] *= al1;
        }

        // store P (A-frag: kstep = nt; elem (row g+8h, col nt*8 + 2tg+e))
#pragma unroll
        for (int nt = 0; nt < 8; nt++) {
#pragma unroll
            for (int e2 = 0; e2 < 4; e2++) {
                int e = e2 & 1, h = e2 >> 1;
                int ss = tg * 2 + e;                 // 0..7
                int addr = nt * 128 + (g * 4 + (ss & 3)) * 4
                         + (((ss >> 2) << 1) | h);
                Pw[addr] = f2tf(s[nt][e2]);
            }
        }
        __syncwarp();

        // ---- O += P @ V ----
#pragma unroll
        for (int ks = 0; ks < 8; ks++) {
            uint4 ap = *(const uint4*)&Pw[ks * 128 + lane * 4];
#pragma unroll
            for (int nt = 0; nt < 16; nt++) {
                uint2 bv = *(const uint2*)&sV[(ks * 16 + nt) * 64 + lane * 2];
                mma4(o[nt], ap, bv);
            }
        }
    }

    // ---- epilogue ----
    int b = bh >> 4;
    int hh = bh & 15;
#pragma unroll
    for (int h = 0; h < 2; h++) {
        float invl = 1.0f / (h ? lrow1 : lrow0);
        int t = q0 + w * 16 + g + h * 8;
        float* op = g_y + ((size_t)(b * Tv + t)) * Cv + hh * HDv;
#pragma unroll
        for (int nt = 0; nt < 16; nt++) {
            int d = nt * 8 + tg * 2;
            *(float2*)&op[d] = make_float2(o[nt][2 * h] * invl, o[nt][2 * h + 1] * invl);
        }
    }
}

// ---------------- launch ----------------
extern "C" void kernel_launch(void* const* d_in, const int* in_sizes, int n_in,
                              void* d_out, int out_size)
{
    const float* x  = (const float*)d_in[0];
    // d_in[1] = mask (causal, known statically; unused)
    const float* wq = (const float*)d_in[2];
    const float* wk = (const float*)d_in[3];
    const float* wv = (const float*)d_in[4];
    const float* wo = (const float*)d_in[5];
    float* out = (float*)d_out;

    dim3 gg(Cv / 128, (Bv * Tv) / 128);  // (16, 64)

    tf32gemm_kernel<<<gg, 256>>>(x, wq, nullptr, 0, 0);
    tf32gemm_kernel<<<gg, 256>>>(x, wk, nullptr, 0, 1);
    tf32gemm_kernel<<<gg, 256>>>(x, wv, nullptr, 0, 2);

    rope_kernel<<<(BHv * Tv * 64) / 256, 256>>>();

    cudaFuncSetAttribute(attn_kernel, cudaFuncAttributeMaxDynamicSharedMemorySize,
                         ATT_SMEM_BYTES);
    attn_kernel<<<dim3(Tv / 64, BHv), 128, ATT_SMEM_BYTES>>>();

    tf32gemm_kernel<<<gg, 256>>>(nullptr, wo, out, 1, 3);
}

// round 4
// speedup vs baseline: 2.0160x; 1.0011x over previous
#include <cuda_runtime.h>
#include <math.h>

#define Bv  4
#define Tv  2048
#define Cv  2048
#define Hv  16
#define HDv 128
#define BHv (Bv*Hv)

// ---------------- scratch (device globals; no allocation allowed) ----------------
__device__ float    g_q[(size_t)BHv * Tv * HDv];   // [b,h,t,d] fp32 then tf32 bits after rope
__device__ float    g_k[(size_t)BHv * Tv * HDv];
__device__ float    g_v[(size_t)BHv * Tv * HDv];   // tf32 bits
__device__ float    g_y[(size_t)Bv * Tv * Cv];     // attention out, tf32 bits
__device__ unsigned g_xt[(size_t)Bv * Tv * Cv];    // x pre-converted to tf32
__device__ unsigned g_wt[(size_t)4 * Cv * Cv];     // wq,wk,wv,wo pre-converted

__device__ __forceinline__ unsigned f2tf(float f) {
    unsigned u;
    asm("cvt.rna.tf32.f32 %0, %1;" : "=r"(u) : "f"(f));
    return u;
}

__device__ __forceinline__ void mma4(float* c, const uint4& a, const uint2& b) {
    asm volatile(
        "mma.sync.aligned.m16n8k8.row.col.f32.tf32.tf32.f32 "
        "{%0,%1,%2,%3}, {%4,%5,%6,%7}, {%8,%9}, {%0,%1,%2,%3};\n"
        : "+f"(c[0]), "+f"(c[1]), "+f"(c[2]), "+f"(c[3])
        : "r"(a.x), "r"(a.y), "r"(a.z), "r"(a.w), "r"(b.x), "r"(b.y));
}

// ---------------- pre-convert fp32 -> tf32 bits ----------------
// dst_sel: 0 -> g_xt, 1 -> g_wt (+dstoff)
__global__ void cvt_kernel(const float* __restrict__ src, int dst_sel, size_t dstoff)
{
    size_t i = ((size_t)blockIdx.x * blockDim.x + threadIdx.x) * 4;
    float4 v = *(const float4*)(src + i);
    uint4 u = make_uint4(f2tf(v.x), f2tf(v.y), f2tf(v.z), f2tf(v.w));
    unsigned* dst = (dst_sel == 0) ? g_xt : (g_wt + dstoff);
    *(uint4*)(dst + i) = u;
}

// ================= tf32 GEMM: out[r,o] = sum_c A[r,c] * W[o,c] =================
// A, W already tf32 bit patterns. Block 128x128, BK=16, 256 threads,
// 8 warps (4x2), warp tile 32x64, fragment-order smem, double buffered.
// src_mode: 0 -> g_xt, 1 -> g_y (tf32 bits)
// dst_mode: 0 -> g_q (fp32), 1 -> g_k (fp32), 2 -> g_v (tf32 bits), 3 -> Oext fp32
__global__ void tf32gemm_kernel(const unsigned* __restrict__ W,
                                float* __restrict__ Oext,
                                int src_mode, int dst_mode)
{
    __shared__ unsigned sA[2][2048];
    __shared__ unsigned sB[2][2048];

    const unsigned* A = (src_mode == 0) ? g_xt : (const unsigned*)g_y;

    int bm = blockIdx.y * 128;
    int bn = blockIdx.x * 128;
    int tid = threadIdx.x;
    int lane = tid & 31;
    int wid = tid >> 5;
    int g = lane >> 2;
    int tg = lane & 3;
    int lr = tid >> 2;          // 0..63
    int lc = (tid & 3) * 4;     // 0,4,8,12

    const unsigned* aptr = A + (size_t)(bm + lr) * Cv + lc;
    const unsigned* bptr = W + (size_t)(bn + lr) * Cv + lc;

    int aoff0 = ((lc >> 3) * 8 + (lr >> 4)) * 128 + (lr & 7) * 16
              + (((lr >> 3) & 1) | (((lc >> 2) & 1) << 1));
    int aoff1 = aoff0 + 512;
    int boff0 = ((lc >> 3) * 16 + (lr >> 3)) * 64 + (lr & 7) * 8 + ((lc >> 2) & 1);
    int boff1 = boff0 + 512;

    int mt0 = (wid & 3) * 2;
    int nt0 = (wid >> 2) * 8;

    float c[2][8][4];
#pragma unroll
    for (int i = 0; i < 2; i++)
#pragma unroll
        for (int j = 0; j < 8; j++)
#pragma unroll
            for (int e = 0; e < 4; e++) c[i][j][e] = 0.0f;

    {
        uint4 va0 = *(const uint4*)(aptr);
        uint4 va1 = *(const uint4*)(aptr + (size_t)64 * Cv);
        uint4 vb0 = *(const uint4*)(bptr);
        uint4 vb1 = *(const uint4*)(bptr + (size_t)64 * Cv);
        sA[0][aoff0 + 0] = va0.x; sA[0][aoff0 + 4]  = va0.y;
        sA[0][aoff0 + 8] = va0.z; sA[0][aoff0 + 12] = va0.w;
        sA[0][aoff1 + 0] = va1.x; sA[0][aoff1 + 4]  = va1.y;
        sA[0][aoff1 + 8] = va1.z; sA[0][aoff1 + 12] = va1.w;
        sB[0][boff0 + 0] = vb0.x; sB[0][boff0 + 2]  = vb0.y;
        sB[0][boff0 + 4] = vb0.z; sB[0][boff0 + 6]  = vb0.w;
        sB[0][boff1 + 0] = vb1.x; sB[0][boff1 + 2]  = vb1.y;
        sB[0][boff1 + 4] = vb1.z; sB[0][boff1 + 6]  = vb1.w;
    }
    __syncthreads();

    const int NIT = Cv / 16;   // 128
    for (int it = 0; it < NIT; it++) {
        uint4 va0, va1, vb0, vb1;
        if (it + 1 < NIT) {
            size_t k0 = (size_t)(it + 1) * 16;
            va0 = *(const uint4*)(aptr + k0);
            va1 = *(const uint4*)(aptr + (size_t)64 * Cv + k0);
            vb0 = *(const uint4*)(bptr + k0);
            vb1 = *(const uint4*)(bptr + (size_t)64 * Cv + k0);
        }

        const unsigned* SA = sA[it & 1];
        const unsigned* SB = sB[it & 1];
#pragma unroll
        for (int ks = 0; ks < 2; ks++) {
            uint4 a0 = *(const uint4*)&SA[(ks * 8 + mt0) * 128 + lane * 4];
            uint4 a1 = *(const uint4*)&SA[(ks * 8 + mt0 + 1) * 128 + lane * 4];
#pragma unroll
            for (int j = 0; j < 8; j++) {
                uint2 b = *(const uint2*)&SB[(ks * 16 + nt0 + j) * 64 + lane * 2];
                mma4(c[0][j], a0, b);
                mma4(c[1][j], a1, b);
            }
        }
        __syncthreads();

        if (it + 1 < NIT) {
            unsigned* WA = sA[(it + 1) & 1];
            unsigned* WB = sB[(it + 1) & 1];
            WA[aoff0 + 0] = va0.x; WA[aoff0 + 4]  = va0.y;
            WA[aoff0 + 8] = va0.z; WA[aoff0 + 12] = va0.w;
            WA[aoff1 + 0] = va1.x; WA[aoff1 + 4]  = va1.y;
            WA[aoff1 + 8] = va1.z; WA[aoff1 + 12] = va1.w;
            WB[boff0 + 0] = vb0.x; WB[boff0 + 2]  = vb0.y;
            WB[boff0 + 4] = vb0.z; WB[boff0 + 6]  = vb0.w;
            WB[boff1 + 0] = vb1.x; WB[boff1 + 2]  = vb1.y;
            WB[boff1 + 4] = vb1.z; WB[boff1 + 6]  = vb1.w;
            __syncthreads();
        }
    }

    int wm = (wid & 3) * 32;
    int wn = (wid >> 2) * 64;

    if (dst_mode == 3) {
#pragma unroll
        for (int i = 0; i < 2; i++)
#pragma unroll
            for (int j = 0; j < 8; j++) {
                int r = bm + wm + i * 16 + g;
                int o = bn + wn + j * 8 + tg * 2;
                *(float2*)&Oext[(size_t)r * Cv + o] = make_float2(c[i][j][0], c[i][j][1]);
                *(float2*)&Oext[(size_t)(r + 8) * Cv + o] = make_float2(c[i][j][2], c[i][j][3]);
            }
    } else {
        float* outp = (dst_mode == 0) ? g_q : (dst_mode == 1) ? g_k : g_v;
        bool cv = (dst_mode == 2);
#pragma unroll
        for (int i = 0; i < 2; i++)
#pragma unroll
            for (int j = 0; j < 8; j++) {
                int r = bm + wm + i * 16 + g;
                int o = bn + wn + j * 8 + tg * 2;
                int b_ = r >> 11;
                int t  = r & 2047;
                int h  = o >> 7;
                int d  = o & 127;
                size_t off = (((size_t)(b_ * Hv + h) * Tv) + t) * HDv + d;
                float v0 = c[i][j][0], v1 = c[i][j][1], v2 = c[i][j][2], v3 = c[i][j][3];
                if (cv) {
                    v0 = __uint_as_float(f2tf(v0)); v1 = __uint_as_float(f2tf(v1));
                    v2 = __uint_as_float(f2tf(v2)); v3 = __uint_as_float(f2tf(v3));
                }
                *(float2*)&outp[off] = make_float2(v0, v1);
                *(float2*)&outp[off + (size_t)8 * HDv] = make_float2(v2, v3);
            }
    }
}

// ---------------- RoPE (in place on g_q, g_k; stores tf32 bits) ----------------
__global__ void rope_kernel()
{
    int idx = blockIdx.x * blockDim.x + threadIdx.x;
    int i  = idx & 63;
    int t  = (idx >> 6) & 2047;
    int bh = idx >> 17;
    if (bh >= BHv) return;

    float inv = (float)pow(10000.0, -(double)i / 64.0);
    float f = (float)t * inv;
    float c = cosf(f), s = sinf(f);

    size_t base = ((size_t)bh * Tv + t) * HDv;
    float q1 = g_q[base + i], q2 = g_q[base + i + 64];
    g_q[base + i]      = __uint_as_float(f2tf(q1 * c - q2 * s));
    g_q[base + i + 64] = __uint_as_float(f2tf(q2 * c + q1 * s));
    float k1 = g_k[base + i], k2 = g_k[base + i + 64];
    g_k[base + i]      = __uint_as_float(f2tf(k1 * c - k2 * s));
    g_k[base + i + 64] = __uint_as_float(f2tf(k2 * c + k1 * s));
}

// ================= TF32 flash attention, causal =================
// CTA: 64 q-rows, 4 warps. q/k/v already tf32 bits -> staging is a pure bit move.
#define ATT_SMEM_U32  (8192 * 3 + 4096)
#define ATT_SMEM_BYTES (ATT_SMEM_U32 * 4)

__global__ void attn_kernel()
{
    extern __shared__ unsigned sm[];
    unsigned* sQ = sm;
    unsigned* sK = sQ + 8192;
    unsigned* sV = sK + 8192;
    unsigned* sP = sV + 8192;

    int bh = blockIdx.y;
    int qb = blockIdx.x;
    int q0 = qb * 64;
    int tid = threadIdx.x;
    int lane = tid & 31;
    int w = tid >> 5;
    int g = lane >> 2;
    int tg = lane & 3;
    size_t base = (size_t)bh * Tv * HDv;

    for (int i = tid; i < 2048; i += 128) {
        int r  = i >> 5;
        int d0 = (i & 31) * 4;
        uint4 v = *(const uint4*)&g_q[base + (size_t)(q0 + r) * HDv + d0];
        int addr = ((d0 >> 3) * 4 + (r >> 4)) * 128 + (r & 7) * 16
                 + (((r >> 3) & 1) | (((d0 >> 2) & 1) << 1));
        sQ[addr + 0] = v.x; sQ[addr + 4]  = v.y;
        sQ[addr + 8] = v.z; sQ[addr + 12] = v.w;
    }

    float o[16][4];
#pragma unroll
    for (int nt = 0; nt < 16; nt++)
#pragma unroll
        for (int e = 0; e < 4; e++) o[nt][e] = 0.0f;
    float mrow0 = -1e30f, mrow1 = -1e30f;
    float lrow0 = 0.0f,   lrow1 = 0.0f;

    const float scale = 0.08838834764831845f;  // 1/sqrt(128)
    unsigned* Pw = sP + w * 1024;

    for (int kt = 0; kt <= qb; kt++) {
        __syncthreads();
        int k0 = kt * 64;
        for (int i = tid; i < 2048; i += 128) {
            int r  = i >> 5;
            int d0 = (i & 31) * 4;
            uint4 vk = *(const uint4*)&g_k[base + (size_t)(k0 + r) * HDv + d0];
            uint4 vv = *(const uint4*)&g_v[base + (size_t)(k0 + r) * HDv + d0];
            int ak = ((d0 >> 3) * 8 + (r >> 3)) * 64 + (r & 7) * 8 + ((d0 >> 2) & 1);
            sK[ak + 0] = vk.x; sK[ak + 2] = vk.y;
            sK[ak + 4] = vk.z; sK[ak + 6] = vk.w;
            int av = ((r >> 3) * 16 + (d0 >> 3)) * 64 + ((d0 & 7) * 4 + (r & 3)) * 2
                   + ((r >> 2) & 1);
            sV[av + 0]  = vv.x; sV[av + 8]  = vv.y;
            sV[av + 16] = vv.z; sV[av + 24] = vv.w;
        }
        __syncthreads();

        float s[8][4];
#pragma unroll
        for (int nt = 0; nt < 8; nt++)
#pragma unroll
            for (int e = 0; e < 4; e++) s[nt][e] = 0.0f;
#pragma unroll
        for (int ks = 0; ks < 16; ks++) {
            uint4 aq = *(const uint4*)&sQ[(ks * 4 + w) * 128 + lane * 4];
#pragma unroll
            for (int nt = 0; nt < 8; nt++) {
                uint2 bk = *(const uint2*)&sK[(ks * 8 + nt) * 64 + lane * 2];
                mma4(s[nt], aq, bk);
            }
        }

        bool diag = (kt == qb);
        int row0 = q0 + w * 16 + g;
#pragma unroll
        for (int nt = 0; nt < 8; nt++) {
#pragma unroll
            for (int e2 = 0; e2 < 4; e2++) {
                float v = s[nt][e2] * scale;
                if (diag) {
                    int col = k0 + nt * 8 + tg * 2 + (e2 & 1);
                    int row = row0 + (e2 >> 1) * 8;
                    if (col > row) v = -1e30f;
                }
                s[nt][e2] = v;
            }
        }

        float mx0 = -1e30f, mx1 = -1e30f;
#pragma unroll
        for (int nt = 0; nt < 8; nt++) {
            mx0 = fmaxf(mx0, fmaxf(s[nt][0], s[nt][1]));
            mx1 = fmaxf(mx1, fmaxf(s[nt][2], s[nt][3]));
        }
        mx0 = fmaxf(mx0, __shfl_xor_sync(0xffffffffu, mx0, 1));
        mx0 = fmaxf(mx0, __shfl_xor_sync(0xffffffffu, mx0, 2));
        mx1 = fmaxf(mx1, __shfl_xor_sync(0xffffffffu, mx1, 1));
        mx1 = fmaxf(mx1, __shfl_xor_sync(0xffffffffu, mx1, 2));

        float mn0 = fmaxf(mrow0, mx0);
        float mn1 = fmaxf(mrow1, mx1);
        float al0 = __expf(mrow0 - mn0);
        float al1 = __expf(mrow1 - mn1);
        mrow0 = mn0; mrow1 = mn1;

        float rs0 = 0.0f, rs1 = 0.0f;
#pragma unroll
        for (int nt = 0; nt < 8; nt++) {
            float p0 = __expf(s[nt][0] - mn0);
            float p1 = __expf(s[nt][1] - mn0);
            float p2 = __expf(s[nt][2] - mn1);
            float p3 = __expf(s[nt][3] - mn1);
            rs0 += p0 + p1; rs1 += p2 + p3;
            s[nt][0] = p0; s[nt][1] = p1; s[nt][2] = p2; s[nt][3] = p3;
        }
        rs0 += __shfl_xor_sync(0xffffffffu, rs0, 1);
        rs0 += __shfl_xor_sync(0xffffffffu, rs0, 2);
        rs1 += __shfl_xor_sync(0xffffffffu, rs1, 1);
        rs1 += __shfl_xor_sync(0xffffffffu, rs1, 2);
        lrow0 = lrow0 * al0 + rs0;
        lrow1 = lrow1 * al1 + rs1;

#pragma unroll
        for (int nt = 0; nt < 16; nt++) {
            o[nt][0] *= al0; o[nt][1] *= al0;
            o[nt][2] *= al1; o[nt][3] *= al1;
        }

#pragma unroll
        for (int nt = 0; nt < 8; nt++) {
#pragma unroll
            for (int e2 = 0; e2 < 4; e2++) {
                int e = e2 & 1, h = e2 >> 1;
                int ss = tg * 2 + e;
                int addr = nt * 128 + (g * 4 + (ss & 3)) * 4
                         + (((ss >> 2) << 1) | h);
                Pw[addr] = f2tf(s[nt][e2]);
            }
        }
        __syncwarp();

#pragma unroll
        for (int ks = 0; ks < 8; ks++) {
            uint4 ap = *(const uint4*)&Pw[ks * 128 + lane * 4];
#pragma unroll
            for (int nt = 0; nt < 16; nt++) {
                uint2 bv = *(const uint2*)&sV[(ks * 16 + nt) * 64 + lane * 2];
                mma4(o[nt], ap, bv);
            }
        }
    }

    int b = bh >> 4;
    int hh = bh & 15;
#pragma unroll
    for (int h = 0; h < 2; h++) {
        float invl = 1.0f / (h ? lrow1 : lrow0);
        int t = q0 + w * 16 + g + h * 8;
        float* op = g_y + ((size_t)(b * Tv + t)) * Cv + hh * HDv;
#pragma unroll
        for (int nt = 0; nt < 16; nt++) {
            int d = nt * 8 + tg * 2;
            op[d]     = __uint_as_float(f2tf(o[nt][2 * h] * invl));
            op[d + 1] = __uint_as_float(f2tf(o[nt][2 * h + 1] * invl));
        }
    }
}

// ---------------- launch ----------------
extern "C" void kernel_launch(void* const* d_in, const int* in_sizes, int n_in,
                              void* d_out, int out_size)
{
    const float* x  = (const float*)d_in[0];
    // d_in[1] = mask (causal, known statically; unused)
    const float* wq = (const float*)d_in[2];
    const float* wk = (const float*)d_in[3];
    const float* wv = (const float*)d_in[4];
    const float* wo = (const float*)d_in[5];
    float* out = (float*)d_out;

    const size_t NX = (size_t)Bv * Tv * Cv;   // 16.7M
    const size_t NW = (size_t)Cv * Cv;        // 4.19M

    cvt_kernel<<<NX / 1024, 256>>>(x, 0, 0);
    cvt_kernel<<<NW / 1024, 256>>>(wq, 1, 0 * NW);
    cvt_kernel<<<NW / 1024, 256>>>(wk, 1, 1 * NW);
    cvt_kernel<<<NW / 1024, 256>>>(wv, 1, 2 * NW);
    cvt_kernel<<<NW / 1024, 256>>>(wo, 1, 3 * NW);

    dim3 gg(Cv / 128, (Bv * Tv) / 128);  // (16, 64)

    // device pointer of g_wt segments passed via offset-from-null trick is not
    // allowed; instead bind via symbol-resolved pointers computed in-kernel:
    // simplest: pass W as g_wt + widx*NW using cudaGetSymbolAddress once.
    static unsigned* wtp = nullptr;
    if (!wtp) cudaGetSymbolAddress((void**)&wtp, g_wt);

    tf32gemm_kernel<<<gg, 256>>>(wtp + 0 * NW, nullptr, 0, 0);
    tf32gemm_kernel<<<gg, 256>>>(wtp + 1 * NW, nullptr, 0, 1);
    tf32gemm_kernel<<<gg, 256>>>(wtp + 2 * NW, nullptr, 0, 2);

    rope_kernel<<<(BHv * Tv * 64) / 256, 256>>>();

    cudaFuncSetAttribute(attn_kernel, cudaFuncAttributeMaxDynamicSharedMemorySize,
                         ATT_SMEM_BYTES);
    attn_kernel<<<dim3(Tv / 64, BHv), 128, ATT_SMEM_BYTES>>>();

    tf32gemm_kernel<<<gg, 256>>>(wtp + 3 * NW, out, 1, 3);
}